// round 1
// baseline (speedup 1.0000x reference)
#include <cuda_runtime.h>
#include <math.h>

#define NTYPES 2
#define NETYPES 2
#define NN 50000
#define FINDIM 128
#define HIDDIM 128
#define NH 4
#define DH 32
#define NL 2
#define NEDGE 400000

__device__ __constant__ int c_esrc[2] = {0, 1};
__device__ __constant__ int c_edst[2] = {1, 0};

// ---- scratch (__device__ globals; no allocation allowed) ----
__device__ float g_h[(size_t)NTYPES * NN * HIDDIM];
__device__ float g_proj[(size_t)NTYPES * NN * 384];
__device__ float g_agg[(size_t)NTYPES * NN * HIDDIM];
__device__ float g_wcat[(size_t)NTYPES * 128 * 384];
__device__ float g_bcat[NTYPES * 384];
__device__ int   g_deg[NETYPES * NN];
__device__ int   g_off[NETYPES * (NN + 1)];
__device__ int   g_cur[NETYPES * NN];
__device__ int   g_srcs[(size_t)NETYPES * NEDGE];
__device__ int   g_last[NTYPES * NN];

__device__ __forceinline__ float gelu_exact(float x) {
    return 0.5f * x * (1.0f + erff(x * 0.7071067811865476f));
}

// ---------------- init ----------------
__global__ void init_kernel() {
    int idx = blockIdx.x * blockDim.x + threadIdx.x;
    if (idx < NETYPES * NN) g_deg[idx] = 0;
    if (idx < NTYPES * NN)  g_last[idx] = -1;
}

// ---------------- CSR build (counting sort by dst) + last-src-edge ----------------
__global__ void edge_count_kernel(const int* __restrict__ ei) {
    int idx = blockIdx.x * blockDim.x + threadIdx.x;
    if (idx >= NETYPES * NEDGE) return;
    int e = idx / NEDGE, j = idx % NEDGE;
    const int* base = ei + (size_t)e * 2 * NEDGE;
    int src = base[j];
    int dst = base[NEDGE + j];
    atomicAdd(&g_deg[e * NN + dst], 1);
    atomicMax(&g_last[c_esrc[e] * NN + src], j);
}

__global__ void scan_kernel() {
    int e = blockIdx.x;
    __shared__ int sh[1024];
    int tidx = threadIdx.x;
    const int CH = (NN + 1023) / 1024;
    int base = tidx * CH;
    int s = 0;
    for (int i = 0; i < CH; i++) { int id = base + i; if (id < NN) s += g_deg[e * NN + id]; }
    sh[tidx] = s;
    __syncthreads();
    for (int o = 1; o < 1024; o <<= 1) {
        int v = (tidx >= o) ? sh[tidx - o] : 0;
        __syncthreads();
        sh[tidx] += v;
        __syncthreads();
    }
    int run = sh[tidx] - s;  // exclusive prefix for this thread's chunk
    for (int i = 0; i < CH; i++) {
        int id = base + i;
        if (id < NN) {
            g_off[e * (NN + 1) + id] = run;
            g_cur[e * NN + id] = run;
            run += g_deg[e * NN + id];
        }
    }
    if (tidx == 1023) g_off[e * (NN + 1) + NN] = sh[1023];
}

__global__ void edge_scatter_kernel(const int* __restrict__ ei) {
    int idx = blockIdx.x * blockDim.x + threadIdx.x;
    if (idx >= NETYPES * NEDGE) return;
    int e = idx / NEDGE, j = idx % NEDGE;
    const int* base = ei + (size_t)e * 2 * NEDGE;
    int src = base[j];
    int dst = base[NEDGE + j];
    int pos = atomicAdd(&g_cur[e * NN + dst], 1);
    g_srcs[(size_t)e * NEDGE + pos] = src;
}

// ---------------- edge-weight scaling (last write wins) ----------------
__global__ void scale_h_kernel(const float* __restrict__ ew) {
    int idx = blockIdx.x * blockDim.x + threadIdx.x;
    if (idx >= NTYPES * NN * 32) return;
    int t = idx / (NN * 32);
    int r = idx % (NN * 32);
    int n = r >> 5;
    int c = (r & 31) * 4;
    int li = g_last[t * NN + n];
    if (li < 0) return;
    int e = 0;
    for (int ee = 0; ee < NETYPES; ee++) if (c_esrc[ee] == t) e = ee;
    float w = 1.f / (1.f + expf(-ew[(size_t)e * NEDGE + li]));
    float4* p = (float4*)(g_h + ((size_t)t * NN + n) * HIDDIM + c);
    float4 v = *p;
    v.x *= w; v.y *= w; v.z *= w; v.w *= w;
    *p = v;
}

// ---------------- compose Wcat = [q_w | k_w@R_att | v_w@R_msg], bcat likewise ----------------
__global__ void compose_kernel(const float* __restrict__ kw, const float* __restrict__ kb,
                               const float* __restrict__ qw, const float* __restrict__ qb,
                               const float* __restrict__ vw, const float* __restrict__ vb,
                               const float* __restrict__ ratt, const float* __restrict__ rmsg,
                               int l) {
    int idx = blockIdx.x * blockDim.x + threadIdx.x;
    const int total = NTYPES * 384 * 129;
    if (idx >= total) return;
    int t = idx / (384 * 129);
    int r = idx % (384 * 129);
    int j = r / 129;
    int i = r % 129;  // i==128 -> bias row
    float val;
    if (j < 128) {
        val = (i < 128) ? qw[(((size_t)l * NTYPES + t) * 128 + i) * 128 + j]
                        : qb[((size_t)l * NTYPES + t) * 128 + j];
    } else {
        bool isK = (j < 256);
        int jo = j - (isK ? 128 : 256);
        int hh = jo >> 5, eo = jo & 31;
        int e = 0;
        for (int ee = 0; ee < NETYPES; ee++) if (c_esrc[ee] == t) e = ee;
        const float* rel = (isK ? ratt : rmsg) +
                           ((((size_t)l * NETYPES + e) * NH + hh) * DH) * DH + eo;
        float s = 0.f;
        if (i < 128) {
            const float* wr = (isK ? kw : vw) + (((size_t)l * NTYPES + t) * 128 + i) * 128 + hh * 32;
            #pragma unroll
            for (int d = 0; d < 32; d++) s += wr[d] * rel[d * 32];
        } else {
            const float* br = (isK ? kb : vb) + ((size_t)l * NTYPES + t) * 128 + hh * 32;
            #pragma unroll
            for (int d = 0; d < 32; d++) s += br[d] * rel[d * 32];
        }
        val = s;
    }
    if (i < 128) g_wcat[((size_t)t * 128 + i) * 384 + j] = val;
    else         g_bcat[t * 384 + j] = val;
}

// ---------------- SGEMM: C[M,Ntot] = epi( actA(A[M,128]) @ W[128,Ntot] + bias ) ----------------
// epi: 0 = bias, 1 = bias+relu, 2 = bias then h_new = beta*c + (1-beta)*resid
template<bool GELU_A>
__global__ void gemm_kernel(const float* __restrict__ A, size_t sA,
                            const float* __restrict__ W, size_t sW,
                            const float* __restrict__ bias, size_t sB,
                            float* __restrict__ C, size_t sC,
                            const float* __restrict__ resid, size_t sR,
                            const float* __restrict__ skipv,
                            int M, int Ntot, int epi) {
    int z = blockIdx.z;
    A += (size_t)z * sA; W += (size_t)z * sW; bias += (size_t)z * sB; C += (size_t)z * sC;
    if (resid) resid += (size_t)z * sR;
    __shared__ float As[8][128];
    __shared__ float Ws[8][132];
    const int tid = threadIdx.x;
    const int m0 = blockIdx.x * 128, n0 = blockIdx.y * 128;
    const int ty = tid >> 4, tx = tid & 15;
    const int arow = tid >> 1, aseg = (tid & 1) * 4;
    const int wrow = tid >> 5, wcol = (tid & 31) * 4;
    float acc[8][8];
    #pragma unroll
    for (int i = 0; i < 8; i++)
        #pragma unroll
        for (int j = 0; j < 8; j++) acc[i][j] = 0.f;

    for (int k0 = 0; k0 < 128; k0 += 8) {
        float4 av = make_float4(0.f, 0.f, 0.f, 0.f);
        int gm = m0 + arow;
        if (gm < M) av = *(const float4*)(A + (size_t)gm * 128 + k0 + aseg);
        if (GELU_A) {
            av.x = gelu_exact(av.x); av.y = gelu_exact(av.y);
            av.z = gelu_exact(av.z); av.w = gelu_exact(av.w);
        }
        float4 wv = *(const float4*)(W + (size_t)(k0 + wrow) * Ntot + n0 + wcol);
        __syncthreads();
        As[aseg + 0][arow] = av.x; As[aseg + 1][arow] = av.y;
        As[aseg + 2][arow] = av.z; As[aseg + 3][arow] = av.w;
        *(float4*)&Ws[wrow][wcol] = wv;
        __syncthreads();
        #pragma unroll
        for (int k = 0; k < 8; k++) {
            float4 a0 = *(const float4*)&As[k][ty * 8];
            float4 a1 = *(const float4*)&As[k][ty * 8 + 4];
            float4 b0 = *(const float4*)&Ws[k][tx * 8];
            float4 b1 = *(const float4*)&Ws[k][tx * 8 + 4];
            float ar[8] = {a0.x, a0.y, a0.z, a0.w, a1.x, a1.y, a1.z, a1.w};
            float br[8] = {b0.x, b0.y, b0.z, b0.w, b1.x, b1.y, b1.z, b1.w};
            #pragma unroll
            for (int i = 0; i < 8; i++)
                #pragma unroll
                for (int j = 0; j < 8; j++) acc[i][j] += ar[i] * br[j];
        }
    }
    float beta = 1.f, omb = 0.f;
    if (epi == 2) {
        float sv = skipv[z];
        beta = 1.f / (1.f + expf(-sv));
        omb = 1.f - beta;
    }
    #pragma unroll
    for (int i = 0; i < 8; i++) {
        int gm = m0 + ty * 8 + i;
        if (gm >= M) continue;
        #pragma unroll
        for (int j = 0; j < 8; j++) {
            int gn = n0 + tx * 8 + j;
            float c = acc[i][j] + bias[gn];
            if (epi == 1) c = fmaxf(c, 0.f);
            else if (epi == 2) c = beta * c + omb * resid[(size_t)gm * 128 + gn];
            C[(size_t)gm * Ntot + gn] = c;
        }
    }
}

// ---------------- attention + aggregation: warp per dst node, online softmax ----------------
__global__ void attn_kernel(const float* __restrict__ relp) {
    int e = blockIdx.y;
    int warp = threadIdx.x >> 5, lane = threadIdx.x & 31;
    int n = blockIdx.x * (blockDim.x >> 5) + warp;
    if (n >= NN) return;
    int t = c_edst[e], s = c_esrc[e];
    const float* projT = g_proj + (size_t)t * NN * 384;
    const float* projS = g_proj + (size_t)s * NN * 384;
    const int* offE = g_off + e * (NN + 1);
    const int* srcE = g_srcs + (size_t)e * NEDGE;
    int g = lane >> 3;                                  // head
    float ascale = relp[e * NH + g] * 0.17677669529663689f;  // rel_p / sqrt(32)
    float4 q4 = *(const float4*)(projT + (size_t)n * 384 + lane * 4);
    int beg = offE[n], end = offE[n + 1];
    float m = -3.0e38f, ssum = 0.f;
    float4 acc = make_float4(0.f, 0.f, 0.f, 0.f);
    for (int p2 = beg; p2 < end; ++p2) {
        int u = srcE[p2];
        const float* rs = projS + (size_t)u * 384;
        float4 k4 = *(const float4*)(rs + 128 + lane * 4);
        float4 v4 = *(const float4*)(rs + 256 + lane * 4);
        float d = q4.x * k4.x + q4.y * k4.y + q4.z * k4.z + q4.w * k4.w;
        d += __shfl_xor_sync(0xffffffffu, d, 1);
        d += __shfl_xor_sync(0xffffffffu, d, 2);
        d += __shfl_xor_sync(0xffffffffu, d, 4);
        float a = d * ascale;
        float nm = fmaxf(m, a);
        float sc = expf(m - nm);
        float pe = expf(a - nm);
        ssum = ssum * sc + pe;
        acc.x = acc.x * sc + pe * v4.x;
        acc.y = acc.y * sc + pe * v4.y;
        acc.z = acc.z * sc + pe * v4.z;
        acc.w = acc.w * sc + pe * v4.w;
        m = nm;
    }
    float inv = 1.f / (ssum + 1e-16f);
    float4 o = make_float4(acc.x * inv, acc.y * inv, acc.z * inv, acc.w * inv);
    *(float4*)(g_agg + ((size_t)t * NN + n) * HIDDIM + lane * 4) = o;
}

// ---------------- launch ----------------
extern "C" void kernel_launch(void* const* d_in, const int* in_sizes, int n_in,
                              void* d_out, int out_size) {
    const float* x       = (const float*)d_in[0];
    const int*   ei      = (const int*)  d_in[1];
    const float* ew      = (const float*)d_in[2];
    const float* lin_w   = (const float*)d_in[3];
    const float* lin_b   = (const float*)d_in[4];
    const float* k_w     = (const float*)d_in[5];
    const float* k_b     = (const float*)d_in[6];
    const float* q_w     = (const float*)d_in[7];
    const float* q_b     = (const float*)d_in[8];
    const float* v_w     = (const float*)d_in[9];
    const float* v_b     = (const float*)d_in[10];
    const float* a_w     = (const float*)d_in[11];
    const float* a_b     = (const float*)d_in[12];
    const float* skip    = (const float*)d_in[13];
    const float* rel_att = (const float*)d_in[14];
    const float* rel_msg = (const float*)d_in[15];
    const float* rel_p   = (const float*)d_in[16];
    float* out = (float*)d_out;

    float *ph, *pproj, *pagg, *pwcat, *pbcat;
    cudaGetSymbolAddress((void**)&ph,    g_h);
    cudaGetSymbolAddress((void**)&pproj, g_proj);
    cudaGetSymbolAddress((void**)&pagg,  g_agg);
    cudaGetSymbolAddress((void**)&pwcat, g_wcat);
    cudaGetSymbolAddress((void**)&pbcat, g_bcat);

    const int MB = (NN + 127) / 128;  // 391

    // CSR + last-edge index
    init_kernel<<<(NETYPES * NN + 255) / 256, 256>>>();
    edge_count_kernel<<<(NETYPES * NEDGE + 255) / 256, 256>>>(ei);
    scan_kernel<<<NETYPES, 1024>>>();
    edge_scatter_kernel<<<(NETYPES * NEDGE + 255) / 256, 256>>>(ei);

    // input projection + relu
    gemm_kernel<false><<<dim3(MB, 1, NTYPES), 256>>>(
        x, (size_t)NN * FINDIM, lin_w, 128 * 128, lin_b, 128,
        ph, (size_t)NN * 128, nullptr, 0, nullptr, NN, 128, 1);

    // sigmoid edge-weight scaling (last write wins)
    scale_h_kernel<<<(NTYPES * NN * 32 + 255) / 256, 256>>>(ew);

    for (int l = 0; l < NL; l++) {
        compose_kernel<<<(NTYPES * 384 * 129 + 255) / 256, 256>>>(
            k_w, k_b, q_w, q_b, v_w, v_b, rel_att, rel_msg, l);

        // fused q | k_rel | v_rel projection
        gemm_kernel<false><<<dim3(MB, 3, NTYPES), 256>>>(
            ph, (size_t)NN * 128, pwcat, 128 * 384, pbcat, 384,
            pproj, (size_t)NN * 384, nullptr, 0, nullptr, NN, 384, 0);

        // attention + message aggregation (both edge types)
        attn_kernel<<<dim3((NN + 7) / 8, NETYPES), 256>>>(rel_p + l * NETYPES * NH);

        // output projection with GELU on A, skip-gated residual
        float* dst = (l == NL - 1) ? out : ph;
        gemm_kernel<true><<<dim3(MB, 1, NTYPES), 256>>>(
            pagg, (size_t)NN * 128, a_w + (size_t)l * NTYPES * 128 * 128, 128 * 128,
            a_b + (size_t)l * NTYPES * 128, 128,
            dst, (size_t)NN * 128, ph, (size_t)NN * 128,
            skip + l * NTYPES, NN, 128, 2);
    }
}

// round 3
// speedup vs baseline: 1.0196x; 1.0196x over previous
#include <cuda_runtime.h>
#include <math.h>
#include <stdint.h>

#define NTYPES 2
#define NETYPES 2
#define NN 50000
#define FINDIM 128
#define HIDDIM 128
#define NH 4
#define DH 32
#define NL 2
#define NEDGE 400000

__device__ __constant__ int c_esrc[2] = {0, 1};
__device__ __constant__ int c_edst[2] = {1, 0};

// ---- scratch (__device__ globals; no allocation allowed) ----
__device__ float g_h[(size_t)NTYPES * NN * HIDDIM];
__device__ float g_proj[(size_t)NTYPES * NN * 384];
__device__ float g_agg[(size_t)NTYPES * NN * HIDDIM];
__device__ float g_wcat[(size_t)NTYPES * 128 * 384];
__device__ float g_bcat[NTYPES * 384];
__device__ int   g_deg[NETYPES * NN];
__device__ int   g_off[NETYPES * (NN + 1)];
__device__ int   g_cur[NETYPES * NN];
__device__ int   g_srcs[(size_t)NETYPES * NEDGE];
__device__ int   g_last[NTYPES * NN];

__device__ __forceinline__ float gelu_exact(float x) {
    return 0.5f * x * (1.0f + erff(x * 0.7071067811865476f));
}

__device__ __forceinline__ uint32_t tf32cvt(float x) {
    uint32_t u;
    asm("cvt.rna.tf32.f32 %0, %1;" : "=r"(u) : "f"(x));
    return u;
}
__device__ __forceinline__ float2 tf32split(float x) {
    uint32_t hi = tf32cvt(x);
    float hif = __uint_as_float(hi);
    uint32_t lo = tf32cvt(x - hif);
    return make_float2(hif, __uint_as_float(lo));
}

// ---------------- init ----------------
__global__ void init_kernel() {
    int idx = blockIdx.x * blockDim.x + threadIdx.x;
    if (idx < NETYPES * NN) g_deg[idx] = 0;
    if (idx < NTYPES * NN)  g_last[idx] = -1;
}

// ---------------- CSR build ----------------
__global__ void edge_count_kernel(const int* __restrict__ ei) {
    int idx = blockIdx.x * blockDim.x + threadIdx.x;
    if (idx >= NETYPES * NEDGE) return;
    int e = idx / NEDGE, j = idx % NEDGE;
    const int* base = ei + (size_t)e * 2 * NEDGE;
    int src = base[j];
    int dst = base[NEDGE + j];
    atomicAdd(&g_deg[e * NN + dst], 1);
    atomicMax(&g_last[c_esrc[e] * NN + src], j);
}

__global__ void scan_kernel() {
    int e = blockIdx.x;
    __shared__ int sh[1024];
    int tidx = threadIdx.x;
    const int CH = (NN + 1023) / 1024;
    int base = tidx * CH;
    int s = 0;
    for (int i = 0; i < CH; i++) { int id = base + i; if (id < NN) s += g_deg[e * NN + id]; }
    sh[tidx] = s;
    __syncthreads();
    for (int o = 1; o < 1024; o <<= 1) {
        int v = (tidx >= o) ? sh[tidx - o] : 0;
        __syncthreads();
        sh[tidx] += v;
        __syncthreads();
    }
    int run = sh[tidx] - s;
    for (int i = 0; i < CH; i++) {
        int id = base + i;
        if (id < NN) {
            g_off[e * (NN + 1) + id] = run;
            g_cur[e * NN + id] = run;
            run += g_deg[e * NN + id];
        }
    }
    if (tidx == 1023) g_off[e * (NN + 1) + NN] = sh[1023];
}

__global__ void edge_scatter_kernel(const int* __restrict__ ei) {
    int idx = blockIdx.x * blockDim.x + threadIdx.x;
    if (idx >= NETYPES * NEDGE) return;
    int e = idx / NEDGE, j = idx % NEDGE;
    const int* base = ei + (size_t)e * 2 * NEDGE;
    int src = base[j];
    int dst = base[NEDGE + j];
    int pos = atomicAdd(&g_cur[e * NN + dst], 1);
    g_srcs[(size_t)e * NEDGE + pos] = src;
}

// ---------------- edge-weight scaling (last write wins) ----------------
__global__ void scale_h_kernel(const float* __restrict__ ew) {
    int idx = blockIdx.x * blockDim.x + threadIdx.x;
    if (idx >= NTYPES * NN * 32) return;
    int t = idx / (NN * 32);
    int r = idx % (NN * 32);
    int n = r >> 5;
    int c = (r & 31) * 4;
    int li = g_last[t * NN + n];
    if (li < 0) return;
    int e = 0;
    for (int ee = 0; ee < NETYPES; ee++) if (c_esrc[ee] == t) e = ee;
    float w = 1.f / (1.f + expf(-ew[(size_t)e * NEDGE + li]));
    float4* p = (float4*)(g_h + ((size_t)t * NN + n) * HIDDIM + c);
    float4 v = *p;
    v.x *= w; v.y *= w; v.z *= w; v.w *= w;
    *p = v;
}

// ---------------- compose Wcat = [q_w | k_w@R_att | v_w@R_msg] ----------------
__global__ void compose_kernel(const float* __restrict__ kw, const float* __restrict__ kb,
                               const float* __restrict__ qw, const float* __restrict__ qb,
                               const float* __restrict__ vw, const float* __restrict__ vb,
                               const float* __restrict__ ratt, const float* __restrict__ rmsg,
                               int l) {
    int idx = blockIdx.x * blockDim.x + threadIdx.x;
    const int total = NTYPES * 384 * 129;
    if (idx >= total) return;
    int t = idx / (384 * 129);
    int r = idx % (384 * 129);
    int j = r / 129;
    int i = r % 129;
    float val;
    if (j < 128) {
        val = (i < 128) ? qw[(((size_t)l * NTYPES + t) * 128 + i) * 128 + j]
                        : qb[((size_t)l * NTYPES + t) * 128 + j];
    } else {
        bool isK = (j < 256);
        int jo = j - (isK ? 128 : 256);
        int hh = jo >> 5, eo = jo & 31;
        int e = 0;
        for (int ee = 0; ee < NETYPES; ee++) if (c_esrc[ee] == t) e = ee;
        const float* rel = (isK ? ratt : rmsg) +
                           ((((size_t)l * NETYPES + e) * NH + hh) * DH) * DH + eo;
        float s = 0.f;
        if (i < 128) {
            const float* wr = (isK ? kw : vw) + (((size_t)l * NTYPES + t) * 128 + i) * 128 + hh * 32;
            #pragma unroll
            for (int d = 0; d < 32; d++) s += wr[d] * rel[d * 32];
        } else {
            const float* br = (isK ? kb : vb) + ((size_t)l * NTYPES + t) * 128 + hh * 32;
            #pragma unroll
            for (int d = 0; d < 32; d++) s += br[d] * rel[d * 32];
        }
        val = s;
    }
    if (i < 128) g_wcat[((size_t)t * 128 + i) * 384 + j] = val;
    else         g_bcat[t * 384 + j] = val;
}

// ---------------- tensor-core GEMM: C = epi( actA(A[M,128]) @ W[128,Ntot] + bias ) ----------------
// Split-TF32 (3 mma terms) for ~fp32 accuracy. BM=128, BN=64, BK=16, 8 warps.
#define MMA_TF32(d, a0, a1, a2, a3, b0, b1) \
    asm volatile("mma.sync.aligned.m16n8k8.row.col.f32.tf32.tf32.f32 " \
                 "{%0,%1,%2,%3},{%4,%5,%6,%7},{%8,%9},{%0,%1,%2,%3};" \
                 : "+f"(d[0]), "+f"(d[1]), "+f"(d[2]), "+f"(d[3]) \
                 : "r"(a0), "r"(a1), "r"(a2), "r"(a3), "r"(b0), "r"(b1))

template<bool GELU_A>
__global__ void __launch_bounds__(256, 2)
gemm_tc_kernel(const float* __restrict__ A, size_t sA,
               const float* __restrict__ W, size_t sW,
               const float* __restrict__ bias, size_t sB,
               float* __restrict__ C, size_t sC,
               const float* __restrict__ resid, size_t sR,
               const float* __restrict__ skipv,
               int M, int Ntot, int epi) {
    int z = blockIdx.z;
    A += (size_t)z * sA; W += (size_t)z * sW; bias += (size_t)z * sB; C += (size_t)z * sC;
    if (resid) resid += (size_t)z * sR;

    __shared__ float2 As2[16][132];  // [k][m] (hi,lo)  16.9KB
    __shared__ float2 Ws2[16][68];   // [k][n] (hi,lo)   8.7KB

    const int tid = threadIdx.x;
    const int warp = tid >> 5, lane = tid & 31;
    const int wm = warp >> 2;        // 0..1  (m: 64 rows each)
    const int wn = warp & 3;         // 0..3  (n: 16 cols each)
    const int lr = lane >> 2;        // 0..7
    const int lc = lane & 3;         // 0..3
    const int m0 = blockIdx.x * 128, n0 = blockIdx.y * 64;

    float acc[4][2][4];
    #pragma unroll
    for (int i = 0; i < 4; i++)
        #pragma unroll
        for (int j = 0; j < 2; j++)
            #pragma unroll
            for (int k = 0; k < 4; k++) acc[i][j][k] = 0.f;

    // fill indices
    const int arow = tid >> 1, akseg = (tid & 1) * 8;   // A: row, 8 k-cols (2x float4)
    const int wkrow = tid >> 4, wn4 = (tid & 15) * 4;   // W: k-row (0..15), 4 n-cols

    for (int k0 = 0; k0 < 128; k0 += 16) {
        // ---- load & split A tile [128 x 16] ----
        int gm = m0 + arow;
        #pragma unroll
        for (int i = 0; i < 2; i++) {
            float4 av = make_float4(0.f, 0.f, 0.f, 0.f);
            if (gm < M) av = *(const float4*)(A + (size_t)gm * 128 + k0 + akseg + i * 4);
            if (GELU_A) {
                av.x = gelu_exact(av.x); av.y = gelu_exact(av.y);
                av.z = gelu_exact(av.z); av.w = gelu_exact(av.w);
            }
            As2[akseg + i * 4 + 0][arow] = tf32split(av.x);
            As2[akseg + i * 4 + 1][arow] = tf32split(av.y);
            As2[akseg + i * 4 + 2][arow] = tf32split(av.z);
            As2[akseg + i * 4 + 3][arow] = tf32split(av.w);
        }
        // ---- load & split W tile [16 x 64] ----
        {
            float4 wv = *(const float4*)(W + (size_t)(k0 + wkrow) * Ntot + n0 + wn4);
            Ws2[wkrow][wn4 + 0] = tf32split(wv.x);
            Ws2[wkrow][wn4 + 1] = tf32split(wv.y);
            Ws2[wkrow][wn4 + 2] = tf32split(wv.z);
            Ws2[wkrow][wn4 + 3] = tf32split(wv.w);
        }
        __syncthreads();

        #pragma unroll
        for (int kk = 0; kk < 16; kk += 8) {
            uint32_t ah[4][4], al[4][4], bh[2][2], bl[2][2];
            #pragma unroll
            for (int mf = 0; mf < 4; mf++) {
                int mb = wm * 64 + mf * 16 + lr;
                float2 v0 = As2[kk + lc][mb];
                float2 v1 = As2[kk + lc][mb + 8];
                float2 v2 = As2[kk + lc + 4][mb];
                float2 v3 = As2[kk + lc + 4][mb + 8];
                ah[mf][0] = __float_as_uint(v0.x); al[mf][0] = __float_as_uint(v0.y);
                ah[mf][1] = __float_as_uint(v1.x); al[mf][1] = __float_as_uint(v1.y);
                ah[mf][2] = __float_as_uint(v2.x); al[mf][2] = __float_as_uint(v2.y);
                ah[mf][3] = __float_as_uint(v3.x); al[mf][3] = __float_as_uint(v3.y);
            }
            #pragma unroll
            for (int nf = 0; nf < 2; nf++) {
                int nb = wn * 16 + nf * 8 + lr;
                float2 w0 = Ws2[kk + lc][nb];
                float2 w1 = Ws2[kk + lc + 4][nb];
                bh[nf][0] = __float_as_uint(w0.x); bl[nf][0] = __float_as_uint(w0.y);
                bh[nf][1] = __float_as_uint(w1.x); bl[nf][1] = __float_as_uint(w1.y);
            }
            #pragma unroll
            for (int mf = 0; mf < 4; mf++)
                #pragma unroll
                for (int nf = 0; nf < 2; nf++) {
                    MMA_TF32(acc[mf][nf], ah[mf][0], ah[mf][1], ah[mf][2], ah[mf][3],
                             bh[nf][0], bh[nf][1]);
                    MMA_TF32(acc[mf][nf], ah[mf][0], ah[mf][1], ah[mf][2], ah[mf][3],
                             bl[nf][0], bl[nf][1]);
                    MMA_TF32(acc[mf][nf], al[mf][0], al[mf][1], al[mf][2], al[mf][3],
                             bh[nf][0], bh[nf][1]);
                }
        }
        __syncthreads();
    }

    float beta = 1.f, omb = 0.f;
    if (epi == 2) {
        float sv = skipv[z];
        beta = 1.f / (1.f + expf(-sv));
        omb = 1.f - beta;
    }
    #pragma unroll
    for (int mf = 0; mf < 4; mf++) {
        #pragma unroll
        for (int rr = 0; rr < 2; rr++) {
            int gm = m0 + wm * 64 + mf * 16 + lr + rr * 8;
            if (gm >= M) continue;
            #pragma unroll
            for (int nf = 0; nf < 2; nf++) {
                int gn = n0 + wn * 16 + nf * 8 + lc * 2;
                float c0 = acc[mf][nf][rr * 2 + 0] + bias[gn];
                float c1 = acc[mf][nf][rr * 2 + 1] + bias[gn + 1];
                if (epi == 1) { c0 = fmaxf(c0, 0.f); c1 = fmaxf(c1, 0.f); }
                else if (epi == 2) {
                    c0 = beta * c0 + omb * resid[(size_t)gm * 128 + gn];
                    c1 = beta * c1 + omb * resid[(size_t)gm * 128 + gn + 1];
                }
                *(float2*)(C + (size_t)gm * Ntot + gn) = make_float2(c0, c1);
            }
        }
    }
}

// ---------------- attention + aggregation: warp per dst node, online softmax ----------------
__global__ void attn_kernel(const float* __restrict__ relp) {
    int e = blockIdx.y;
    int warp = threadIdx.x >> 5, lane = threadIdx.x & 31;
    int n = blockIdx.x * (blockDim.x >> 5) + warp;
    if (n >= NN) return;
    int t = c_edst[e], s = c_esrc[e];
    const float* projT = g_proj + (size_t)t * NN * 384;
    const float* projS = g_proj + (size_t)s * NN * 384;
    const int* offE = g_off + e * (NN + 1);
    const int* srcE = g_srcs + (size_t)e * NEDGE;
    int g = lane >> 3;
    float ascale = relp[e * NH + g] * 0.17677669529663689f;
    float4 q4 = *(const float4*)(projT + (size_t)n * 384 + lane * 4);
    int beg = offE[n], end = offE[n + 1];
    float m = -3.0e38f, ssum = 0.f;
    float4 acc = make_float4(0.f, 0.f, 0.f, 0.f);
    for (int p2 = beg; p2 < end; ++p2) {
        int u = srcE[p2];
        const float* rs = projS + (size_t)u * 384;
        float4 k4 = *(const float4*)(rs + 128 + lane * 4);
        float4 v4 = *(const float4*)(rs + 256 + lane * 4);
        float d = q4.x * k4.x + q4.y * k4.y + q4.z * k4.z + q4.w * k4.w;
        d += __shfl_xor_sync(0xffffffffu, d, 1);
        d += __shfl_xor_sync(0xffffffffu, d, 2);
        d += __shfl_xor_sync(0xffffffffu, d, 4);
        float a = d * ascale;
        float nm = fmaxf(m, a);
        float sc = expf(m - nm);
        float pe = expf(a - nm);
        ssum = ssum * sc + pe;
        acc.x = acc.x * sc + pe * v4.x;
        acc.y = acc.y * sc + pe * v4.y;
        acc.z = acc.z * sc + pe * v4.z;
        acc.w = acc.w * sc + pe * v4.w;
        m = nm;
    }
    float inv = 1.f / (ssum + 1e-16f);
    float4 o = make_float4(acc.x * inv, acc.y * inv, acc.z * inv, acc.w * inv);
    *(float4*)(g_agg + ((size_t)t * NN + n) * HIDDIM + lane * 4) = o;
}

// ---------------- launch ----------------
extern "C" void kernel_launch(void* const* d_in, const int* in_sizes, int n_in,
                              void* d_out, int out_size) {
    const float* x       = (const float*)d_in[0];
    const int*   ei      = (const int*)  d_in[1];
    const float* ew      = (const float*)d_in[2];
    const float* lin_w   = (const float*)d_in[3];
    const float* lin_b   = (const float*)d_in[4];
    const float* k_w     = (const float*)d_in[5];
    const float* k_b     = (const float*)d_in[6];
    const float* q_w     = (const float*)d_in[7];
    const float* q_b     = (const float*)d_in[8];
    const float* v_w     = (const float*)d_in[9];
    const float* v_b     = (const float*)d_in[10];
    const float* a_w     = (const float*)d_in[11];
    const float* a_b     = (const float*)d_in[12];
    const float* skip    = (const float*)d_in[13];
    const float* rel_att = (const float*)d_in[14];
    const float* rel_msg = (const float*)d_in[15];
    const float* rel_p   = (const float*)d_in[16];
    float* out = (float*)d_out;

    float *ph, *pproj, *pagg, *pwcat, *pbcat;
    cudaGetSymbolAddress((void**)&ph,    g_h);
    cudaGetSymbolAddress((void**)&pproj, g_proj);
    cudaGetSymbolAddress((void**)&pagg,  g_agg);
    cudaGetSymbolAddress((void**)&pwcat, g_wcat);
    cudaGetSymbolAddress((void**)&pbcat, g_bcat);

    const int MB = (NN + 127) / 128;  // 391

    init_kernel<<<(NETYPES * NN + 255) / 256, 256>>>();
    edge_count_kernel<<<(NETYPES * NEDGE + 255) / 256, 256>>>(ei);
    scan_kernel<<<NETYPES, 1024>>>();
    edge_scatter_kernel<<<(NETYPES * NEDGE + 255) / 256, 256>>>(ei);

    // input projection + relu
    gemm_tc_kernel<false><<<dim3(MB, 2, NTYPES), 256>>>(
        x, (size_t)NN * FINDIM, lin_w, 128 * 128, lin_b, 128,
        ph, (size_t)NN * 128, nullptr, 0, nullptr, NN, 128, 1);

    scale_h_kernel<<<(NTYPES * NN * 32 + 255) / 256, 256>>>(ew);

    for (int l = 0; l < NL; l++) {
        compose_kernel<<<(NTYPES * 384 * 129 + 255) / 256, 256>>>(
            k_w, k_b, q_w, q_b, v_w, v_b, rel_att, rel_msg, l);

        // fused q | k_rel | v_rel projection
        gemm_tc_kernel<false><<<dim3(MB, 6, NTYPES), 256>>>(
            ph, (size_t)NN * 128, pwcat, 128 * 384, pbcat, 384,
            pproj, (size_t)NN * 384, nullptr, 0, nullptr, NN, 384, 0);

        attn_kernel<<<dim3((NN + 7) / 8, NETYPES), 256>>>(rel_p + l * NETYPES * NH);

        float* dst = (l == NL - 1) ? out : ph;
        gemm_tc_kernel<true><<<dim3(MB, 2, NTYPES), 256>>>(
            pagg, (size_t)NN * 128, a_w + (size_t)l * NTYPES * 128 * 128, 128 * 128,
            a_b + (size_t)l * NTYPES * 128, 128,
            dst, (size_t)NN * 128, ph, (size_t)NN * 128,
            skip + l * NTYPES, NN, 128, 2);
    }
}

// round 5
// speedup vs baseline: 1.6118x; 1.5808x over previous
#include <cuda_runtime.h>
#include <cuda_bf16.h>
#include <math.h>
#include <stdint.h>

#define NTYPES 2
#define NETYPES 2
#define NN 50000
#define FINDIM 128
#define HIDDIM 128
#define NH 4
#define DH 32
#define NL 2
#define NEDGE 400000
#define MTILES 3125   // NN / 16 exactly

__device__ __constant__ int c_esrc[2] = {0, 1};
__device__ __constant__ int c_edst[2] = {1, 0};

// ---- scratch (__device__ globals; no allocation allowed) ----
__device__ float g_h[(size_t)NTYPES * NN * HIDDIM];
__device__ float g_proj[(size_t)NTYPES * NN * 384];
__device__ float g_agg[(size_t)NTYPES * NN * HIDDIM];
__device__ float g_wcat[(size_t)NTYPES * 128 * 384];
__device__ float g_bcat[NTYPES * 384];
__device__ uint8_t g_bsplit[(size_t)NTYPES * 3 * 65536];       // B fragment images
// A fragment images: [z][mt][s][lane] 16B  (hi and lo separate)
__device__ uint4 g_pkA_hi[(size_t)NTYPES * MTILES * 8 * 32];
__device__ uint4 g_pkA_lo[(size_t)NTYPES * MTILES * 8 * 32];
__device__ uint4 g_pkH_hi[(size_t)NTYPES * MTILES * 8 * 32];
__device__ uint4 g_pkH_lo[(size_t)NTYPES * MTILES * 8 * 32];
__device__ int   g_deg[NETYPES * NN];
__device__ int   g_off[NETYPES * (NN + 1)];
__device__ int   g_cur[NETYPES * NN];
__device__ int   g_srcs[(size_t)NETYPES * NEDGE];
__device__ int   g_last[NTYPES * NN];

__device__ __forceinline__ float gelu_exact(float x) {
    return 0.5f * x * (1.0f + erff(x * 0.7071067811865476f));
}

// split x,y into bf16 hi pair (packed b16x2, x in low half) + lo pair
__device__ __forceinline__ uint32_t split2(float x, float y, uint32_t& lo) {
    __nv_bfloat16 hx = __float2bfloat16(x), hy = __float2bfloat16(y);
    float rx = x - __bfloat162float(hx);
    float ry = y - __bfloat162float(hy);
    __nv_bfloat16 lx = __float2bfloat16(rx), ly = __float2bfloat16(ry);
    uint16_t uhx = *(uint16_t*)&hx, uhy = *(uint16_t*)&hy;
    uint16_t ulx = *(uint16_t*)&lx, uly = *(uint16_t*)&ly;
    lo = ((uint32_t)uly << 16) | ulx;
    return ((uint32_t)uhy << 16) | uhx;
}

#define MMA_BF16(d, a, b0, b1) \
    asm volatile("mma.sync.aligned.m16n8k16.row.col.f32.bf16.bf16.f32 " \
                 "{%0,%1,%2,%3},{%4,%5,%6,%7},{%8,%9},{%0,%1,%2,%3};" \
                 : "+f"((d)[0]), "+f"((d)[1]), "+f"((d)[2]), "+f"((d)[3]) \
                 : "r"((a).x), "r"((a).y), "r"((a).z), "r"((a).w), "r"(b0), "r"(b1))

// ---------------- init ----------------
__global__ void init_kernel() {
    int idx = blockIdx.x * blockDim.x + threadIdx.x;
    if (idx < NETYPES * NN) g_deg[idx] = 0;
    if (idx < NTYPES * NN)  g_last[idx] = -1;
}

// ---------------- CSR build ----------------
__global__ void edge_count_kernel(const int* __restrict__ ei) {
    int idx = blockIdx.x * blockDim.x + threadIdx.x;
    if (idx >= NETYPES * NEDGE) return;
    int e = idx / NEDGE, j = idx % NEDGE;
    const int* base = ei + (size_t)e * 2 * NEDGE;
    int src = base[j];
    int dst = base[NEDGE + j];
    atomicAdd(&g_deg[e * NN + dst], 1);
    atomicMax(&g_last[c_esrc[e] * NN + src], j);
}

__global__ void scan_kernel() {
    int e = blockIdx.x;
    __shared__ int sh[1024];
    int tidx = threadIdx.x;
    const int CH = (NN + 1023) / 1024;
    int base = tidx * CH;
    int s = 0;
    for (int i = 0; i < CH; i++) { int id = base + i; if (id < NN) s += g_deg[e * NN + id]; }
    sh[tidx] = s;
    __syncthreads();
    for (int o = 1; o < 1024; o <<= 1) {
        int v = (tidx >= o) ? sh[tidx - o] : 0;
        __syncthreads();
        sh[tidx] += v;
        __syncthreads();
    }
    int run = sh[tidx] - s;
    for (int i = 0; i < CH; i++) {
        int id = base + i;
        if (id < NN) {
            g_off[e * (NN + 1) + id] = run;
            g_cur[e * NN + id] = run;
            run += g_deg[e * NN + id];
        }
    }
    if (tidx == 1023) g_off[e * (NN + 1) + NN] = sh[1023];
}

__global__ void edge_scatter_kernel(const int* __restrict__ ei) {
    int idx = blockIdx.x * blockDim.x + threadIdx.x;
    if (idx >= NETYPES * NEDGE) return;
    int e = idx / NEDGE, j = idx % NEDGE;
    const int* base = ei + (size_t)e * 2 * NEDGE;
    int src = base[j];
    int dst = base[NEDGE + j];
    int pos = atomicAdd(&g_cur[e * NN + dst], 1);
    g_srcs[(size_t)e * NEDGE + pos] = src;
}

// ---------------- edge-weight scaling (last write wins) ----------------
__global__ void scale_h_kernel(const float* __restrict__ ew) {
    int idx = blockIdx.x * blockDim.x + threadIdx.x;
    if (idx >= NTYPES * NN * 32) return;
    int t = idx / (NN * 32);
    int r = idx % (NN * 32);
    int n = r >> 5;
    int c = (r & 31) * 4;
    int li = g_last[t * NN + n];
    if (li < 0) return;
    int e = 0;
    for (int ee = 0; ee < NETYPES; ee++) if (c_esrc[ee] == t) e = ee;
    float w = 1.f / (1.f + expf(-ew[(size_t)e * NEDGE + li]));
    float4* p = (float4*)(g_h + ((size_t)t * NN + n) * HIDDIM + c);
    float4 v = *p;
    v.x *= w; v.y *= w; v.z *= w; v.w *= w;
    *p = v;
}

// ---------------- compose Wcat = [q_w | k_w@R_att | v_w@R_msg] ----------------
__global__ void compose_kernel(const float* __restrict__ kw, const float* __restrict__ kb,
                               const float* __restrict__ qw, const float* __restrict__ qb,
                               const float* __restrict__ vw, const float* __restrict__ vb,
                               const float* __restrict__ ratt, const float* __restrict__ rmsg,
                               int l) {
    int idx = blockIdx.x * blockDim.x + threadIdx.x;
    const int total = NTYPES * 384 * 129;
    if (idx >= total) return;
    int t = idx / (384 * 129);
    int r = idx % (384 * 129);
    int j = r / 129;
    int i = r % 129;
    float val;
    if (j < 128) {
        val = (i < 128) ? qw[(((size_t)l * NTYPES + t) * 128 + i) * 128 + j]
                        : qb[((size_t)l * NTYPES + t) * 128 + j];
    } else {
        bool isK = (j < 256);
        int jo = j - (isK ? 128 : 256);
        int hh = jo >> 5, eo = jo & 31;
        int e = 0;
        for (int ee = 0; ee < NETYPES; ee++) if (c_esrc[ee] == t) e = ee;
        const float* rel = (isK ? ratt : rmsg) +
                           ((((size_t)l * NETYPES + e) * NH + hh) * DH) * DH + eo;
        float s = 0.f;
        if (i < 128) {
            const float* wr = (isK ? kw : vw) + (((size_t)l * NTYPES + t) * 128 + i) * 128 + hh * 32;
            #pragma unroll
            for (int d = 0; d < 32; d++) s += wr[d] * rel[d * 32];
        } else {
            const float* br = (isK ? kb : vb) + ((size_t)l * NTYPES + t) * 128 + hh * 32;
            #pragma unroll
            for (int d = 0; d < 32; d++) s += br[d] * rel[d * 32];
        }
        val = s;
    }
    if (i < 128) g_wcat[((size_t)t * 128 + i) * 384 + j] = val;
    else         g_bcat[t * 384 + j] = val;
}

// ---------------- A split+pack: fp32 [z][NN][128] -> mma A-fragment images ----------------
// Image layout: [z][mt][s][lane] x 16B. Thread's 16B = regs {a0,a1,a2,a3} for (mt,s).
template<bool GELU>
__global__ void split_pack_kernel(const float* __restrict__ src,
                                  uint4* __restrict__ dhi, uint4* __restrict__ dlo) {
    int idx = blockIdx.x * blockDim.x + threadIdx.x;
    const int total = NTYPES * MTILES * 8 * 32;
    if (idx >= total) return;
    int lane = idx & 31;
    int s = (idx >> 5) & 7;
    int mt = (idx >> 8) % MTILES;
    int z = idx / (MTILES * 8 * 32);
    int g = lane >> 2, tig = lane & 3;
    int r0 = mt * 16 + g;
    int c0 = s * 16 + tig * 2;
    const float* S = src + (size_t)z * NN * 128;
    float2 p00 = *(const float2*)(S + (size_t)r0 * 128 + c0);
    float2 p10 = *(const float2*)(S + (size_t)(r0 + 8) * 128 + c0);
    float2 p01 = *(const float2*)(S + (size_t)r0 * 128 + c0 + 8);
    float2 p11 = *(const float2*)(S + (size_t)(r0 + 8) * 128 + c0 + 8);
    if (GELU) {
        p00.x = gelu_exact(p00.x); p00.y = gelu_exact(p00.y);
        p10.x = gelu_exact(p10.x); p10.y = gelu_exact(p10.y);
        p01.x = gelu_exact(p01.x); p01.y = gelu_exact(p01.y);
        p11.x = gelu_exact(p11.x); p11.y = gelu_exact(p11.y);
    }
    uint4 hi, lo;
    hi.x = split2(p00.x, p00.y, lo.x);
    hi.y = split2(p10.x, p10.y, lo.y);
    hi.z = split2(p01.x, p01.y, lo.z);
    hi.w = split2(p11.x, p11.y, lo.w);
    size_t o = (((size_t)z * MTILES + mt) * 8 + s) * 32 + lane;
    dhi[o] = hi;
    dlo[o] = lo;
}

// ---------------- B prep: fp32 W[k][n] -> mma B-fragment images (hi+lo interleaved) ----------------
// Image per (z,ntile): [(s*16+f)][lane] x 16B = {bhi0, bhi1, blo0, blo1}.
__global__ void prep_b_kernel(const float* __restrict__ Wsrc, int Nout, int zstride) {
    int idx = blockIdx.x * blockDim.x + threadIdx.x;
    const int ntl = Nout >> 7;
    const int total = NTYPES * ntl * 8 * 16 * 32;
    if (idx >= total) return;
    int lane = idx & 31;
    int f = (idx >> 5) & 15;
    int s = (idx >> 9) & 7;
    int nt = (idx >> 12) % ntl;
    int z = idx / (ntl * 8 * 16 * 32);
    int g = lane >> 2, tig = lane & 3;
    int n = nt * 128 + f * 8 + g;
    int k0 = s * 16 + tig * 2;
    const float* W = Wsrc + (size_t)z * zstride;
    float w00 = W[(size_t)k0 * Nout + n];
    float w01 = W[(size_t)(k0 + 1) * Nout + n];
    float w10 = W[(size_t)(k0 + 8) * Nout + n];
    float w11 = W[(size_t)(k0 + 9) * Nout + n];
    uint4 q;
    q.x = split2(w00, w01, q.z);
    q.y = split2(w10, w11, q.w);
    uint4* img = (uint4*)(g_bsplit + ((size_t)z * ntl + nt) * 65536);
    img[(s * 16 + f) * 32 + lane] = q;
}

// ---------------- bf16 3-term mma GEMM: C[128,128] tile ----------------
// A from fragment-packed images, B from fragment-packed image via smem.
// 8 warps: wm 0..3 (32 rows), wn 0..1 (64 cols). epi: 0 none, 1 relu, 2 skip-residual.
__global__ void __launch_bounds__(256, 2)
gemm_mma(const uint4* __restrict__ Ahi, const uint4* __restrict__ Alo,
         const float* __restrict__ bias, int sB,
         float* __restrict__ C, size_t sC,
         const float* __restrict__ resid, size_t sR,
         const float* __restrict__ skipv,
         int Ntot, int epi) {
    extern __shared__ uint4 Bs[];  // 4096 x 16B = 64KB
    const int z = blockIdx.z, nt = blockIdx.y;
    const int tid = threadIdx.x, warp = tid >> 5, lane = tid & 31;
    const int wm = warp >> 1, wn = warp & 1;
    const int g = lane >> 2, tig = lane & 3;

    // copy B image to smem
    {
        const uint4* Bimg = (const uint4*)(g_bsplit + ((size_t)z * gridDim.y + nt) * 65536);
        #pragma unroll
        for (int i = 0; i < 16; i++) Bs[tid + i * 256] = Bimg[tid + i * 256];
    }
    __syncthreads();

    const int mt0 = blockIdx.x * 8 + wm * 2;
    float acc[2][8][4];
    #pragma unroll
    for (int a = 0; a < 2; a++)
        #pragma unroll
        for (int b = 0; b < 8; b++)
            #pragma unroll
            for (int c = 0; c < 4; c++) acc[a][b][c] = 0.f;

    uint4 aH[2], aL[2], nHbuf[2], nLbuf[2];
    const uint4 zero4 = make_uint4(0, 0, 0, 0);
    #pragma unroll
    for (int mt = 0; mt < 2; mt++) {
        int mtg = mt0 + mt;
        if (mtg < MTILES) {
            size_t o = (((size_t)z * MTILES + mtg) * 8 + 0) * 32 + lane;
            aH[mt] = Ahi[o]; aL[mt] = Alo[o];
        } else { aH[mt] = zero4; aL[mt] = zero4; }
    }

    for (int s = 0; s < 8; s++) {
        if (s < 7) {
            #pragma unroll
            for (int mt = 0; mt < 2; mt++) {
                int mtg = mt0 + mt;
                if (mtg < MTILES) {
                    size_t o = (((size_t)z * MTILES + mtg) * 8 + (s + 1)) * 32 + lane;
                    nHbuf[mt] = Ahi[o]; nLbuf[mt] = Alo[o];
                } else { nHbuf[mt] = zero4; nLbuf[mt] = zero4; }
            }
        }
        #pragma unroll
        for (int f = 0; f < 8; f++) {
            uint4 q = Bs[(s * 16 + wn * 8 + f) * 32 + lane];
            #pragma unroll
            for (int mt = 0; mt < 2; mt++) {
                MMA_BF16(acc[mt][f], aH[mt], q.x, q.y);   // ah*bh
                MMA_BF16(acc[mt][f], aH[mt], q.z, q.w);   // ah*bl
                MMA_BF16(acc[mt][f], aL[mt], q.x, q.y);   // al*bh
            }
        }
        #pragma unroll
        for (int mt = 0; mt < 2; mt++) { aH[mt] = nHbuf[mt]; aL[mt] = nLbuf[mt]; }
    }

    // ---- epilogue ----
    const float* biasz = bias + (size_t)z * sB;
    float* Cz = C + (size_t)z * sC;
    const float* residz = resid ? resid + (size_t)z * sR : nullptr;
    float beta = 1.f, omb = 0.f;
    if (epi == 2) {
        float sv = skipv[z];
        beta = 1.f / (1.f + expf(-sv));
        omb = 1.f - beta;
    }
    const int n0 = nt * 128 + wn * 64;
    #pragma unroll
    for (int mt = 0; mt < 2; mt++) {
        int mtg = mt0 + mt;
        if (mtg >= MTILES) continue;
        int r0 = mtg * 16 + g;
        #pragma unroll
        for (int f = 0; f < 8; f++) {
            int c = n0 + f * 8 + tig * 2;
            float2 b2 = *(const float2*)(biasz + c);
            float v0 = acc[mt][f][0] + b2.x;
            float v1 = acc[mt][f][1] + b2.y;
            float v2 = acc[mt][f][2] + b2.x;
            float v3 = acc[mt][f][3] + b2.y;
            if (epi == 1) {
                v0 = fmaxf(v0, 0.f); v1 = fmaxf(v1, 0.f);
                v2 = fmaxf(v2, 0.f); v3 = fmaxf(v3, 0.f);
            } else if (epi == 2) {
                float2 ra = *(const float2*)(residz + (size_t)r0 * 128 + c);
                float2 rb = *(const float2*)(residz + (size_t)(r0 + 8) * 128 + c);
                v0 = beta * v0 + omb * ra.x;
                v1 = beta * v1 + omb * ra.y;
                v2 = beta * v2 + omb * rb.x;
                v3 = beta * v3 + omb * rb.y;
            }
            *(float2*)(Cz + (size_t)r0 * Ntot + c) = make_float2(v0, v1);
            *(float2*)(Cz + (size_t)(r0 + 8) * Ntot + c) = make_float2(v2, v3);
        }
    }
}

// ---------------- attention + aggregation: warp per dst node, online softmax ----------------
__global__ void attn_kernel(const float* __restrict__ relp) {
    int e = blockIdx.y;
    int warp = threadIdx.x >> 5, lane = threadIdx.x & 31;
    int n = blockIdx.x * (blockDim.x >> 5) + warp;
    if (n >= NN) return;
    int t = c_edst[e], s = c_esrc[e];
    const float* projT = g_proj + (size_t)t * NN * 384;
    const float* projS = g_proj + (size_t)s * NN * 384;
    const int* offE = g_off + e * (NN + 1);
    const int* srcE = g_srcs + (size_t)e * NEDGE;
    int g = lane >> 3;
    float ascale = relp[e * NH + g] * 0.17677669529663689f;
    float4 q4 = *(const float4*)(projT + (size_t)n * 384 + lane * 4);
    int beg = offE[n], end = offE[n + 1];
    float m = -3.0e38f, ssum = 0.f;
    float4 acc = make_float4(0.f, 0.f, 0.f, 0.f);
    for (int p2 = beg; p2 < end; ++p2) {
        int u = srcE[p2];
        const float* rs = projS + (size_t)u * 384;
        float4 k4 = *(const float4*)(rs + 128 + lane * 4);
        float4 v4 = *(const float4*)(rs + 256 + lane * 4);
        float d = q4.x * k4.x + q4.y * k4.y + q4.z * k4.z + q4.w * k4.w;
        d += __shfl_xor_sync(0xffffffffu, d, 1);
        d += __shfl_xor_sync(0xffffffffu, d, 2);
        d += __shfl_xor_sync(0xffffffffu, d, 4);
        float a = d * ascale;
        float nm = fmaxf(m, a);
        float sc = expf(m - nm);
        float pe = expf(a - nm);
        ssum = ssum * sc + pe;
        acc.x = acc.x * sc + pe * v4.x;
        acc.y = acc.y * sc + pe * v4.y;
        acc.z = acc.z * sc + pe * v4.z;
        acc.w = acc.w * sc + pe * v4.w;
        m = nm;
    }
    float inv = 1.f / (ssum + 1e-16f);
    float4 o = make_float4(acc.x * inv, acc.y * inv, acc.z * inv, acc.w * inv);
    *(float4*)(g_agg + ((size_t)t * NN + n) * HIDDIM + lane * 4) = o;
}

// ---------------- launch ----------------
extern "C" void kernel_launch(void* const* d_in, const int* in_sizes, int n_in,
                              void* d_out, int out_size) {
    const float* x       = (const float*)d_in[0];
    const int*   ei      = (const int*)  d_in[1];
    const float* ew      = (const float*)d_in[2];
    const float* lin_w   = (const float*)d_in[3];
    const float* lin_b   = (const float*)d_in[4];
    const float* k_w     = (const float*)d_in[5];
    const float* k_b     = (const float*)d_in[6];
    const float* q_w     = (const float*)d_in[7];
    const float* q_b     = (const float*)d_in[8];
    const float* v_w     = (const float*)d_in[9];
    const float* v_b     = (const float*)d_in[10];
    const float* a_w     = (const float*)d_in[11];
    const float* a_b     = (const float*)d_in[12];
    const float* skip    = (const float*)d_in[13];
    const float* rel_att = (const float*)d_in[14];
    const float* rel_msg = (const float*)d_in[15];
    const float* rel_p   = (const float*)d_in[16];
    float* out = (float*)d_out;

    float *ph, *pproj, *pagg, *pwcat, *pbcat;
    uint4 *pAh, *pAl, *pHh, *pHl;
    cudaGetSymbolAddress((void**)&ph,    g_h);
    cudaGetSymbolAddress((void**)&pproj, g_proj);
    cudaGetSymbolAddress((void**)&pagg,  g_agg);
    cudaGetSymbolAddress((void**)&pwcat, g_wcat);
    cudaGetSymbolAddress((void**)&pbcat, g_bcat);
    cudaGetSymbolAddress((void**)&pAh,   g_pkA_hi);
    cudaGetSymbolAddress((void**)&pAl,   g_pkA_lo);
    cudaGetSymbolAddress((void**)&pHh,   g_pkH_hi);
    cudaGetSymbolAddress((void**)&pHl,   g_pkH_lo);

    static int smem_set = 0;
    const int SMEM_GEMM = 65536;
    if (!smem_set) {
        cudaFuncSetAttribute(gemm_mma, cudaFuncAttributeMaxDynamicSharedMemorySize, SMEM_GEMM);
        smem_set = 1;
    }

    const int MB = (NN + 127) / 128;  // 391
    const int PACK_T = NTYPES * MTILES * 8 * 32;

    init_kernel<<<(NETYPES * NN + 255) / 256, 256>>>();
    edge_count_kernel<<<(NETYPES * NEDGE + 255) / 256, 256>>>(ei);
    scan_kernel<<<NETYPES, 1024>>>();
    edge_scatter_kernel<<<(NETYPES * NEDGE + 255) / 256, 256>>>(ei);

    // input projection + relu
    split_pack_kernel<false><<<(PACK_T + 255) / 256, 256>>>(x, pAh, pAl);
    prep_b_kernel<<<(NTYPES * 1 * 4096 + 255) / 256, 256>>>(lin_w, 128, 128 * 128);
    gemm_mma<<<dim3(MB, 1, NTYPES), 256, SMEM_GEMM>>>(
        pAh, pAl, lin_b, 128, ph, (size_t)NN * 128, nullptr, 0, nullptr, 128, 1);

    scale_h_kernel<<<(NTYPES * NN * 32 + 255) / 256, 256>>>(ew);
    split_pack_kernel<false><<<(PACK_T + 255) / 256, 256>>>(ph, pHh, pHl);

    for (int l = 0; l < NL; l++) {
        compose_kernel<<<(NTYPES * 384 * 129 + 255) / 256, 256>>>(
            k_w, k_b, q_w, q_b, v_w, v_b, rel_att, rel_msg, l);

        // fused q | k_rel | v_rel projection
        prep_b_kernel<<<(NTYPES * 3 * 4096 + 255) / 256, 256>>>(pwcat, 384, 128 * 384);
        gemm_mma<<<dim3(MB, 3, NTYPES), 256, SMEM_GEMM>>>(
            pHh, pHl, pbcat, 384, pproj, (size_t)NN * 384, nullptr, 0, nullptr, 384, 0);

        attn_kernel<<<dim3((NN + 7) / 8, NETYPES), 256>>>(rel_p + l * NETYPES * NH);

        // output projection: gelu folded into split_pack, skip-residual in epilogue
        split_pack_kernel<true><<<(PACK_T + 255) / 256, 256>>>(pagg, pAh, pAl);
        prep_b_kernel<<<(NTYPES * 1 * 4096 + 255) / 256, 256>>>(
            a_w + (size_t)l * NTYPES * 128 * 128, 128, 128 * 128);
        float* dst = (l == NL - 1) ? out : ph;
        gemm_mma<<<dim3(MB, 1, NTYPES), 256, SMEM_GEMM>>>(
            pAh, pAl, a_b + (size_t)l * NTYPES * 128, 128,
            dst, (size_t)NN * 128, ph, (size_t)NN * 128,
            skip + l * NTYPES, 128, 2);

        if (l == 0)
            split_pack_kernel<false><<<(PACK_T + 255) / 256, 256>>>(ph, pHh, pHl);
    }
}

// round 6
// speedup vs baseline: 1.9911x; 1.2353x over previous
#include <cuda_runtime.h>
#include <cuda_bf16.h>
#include <math.h>
#include <stdint.h>

#define NTYPES 2
#define NETYPES 2
#define NN 50000
#define FINDIM 128
#define HIDDIM 128
#define NH 4
#define DH 32
#define NL 2
#define NEDGE 400000
#define MTILES 3125   // NN / 16 exactly

__device__ __constant__ int c_esrc[2] = {0, 1};
__device__ __constant__ int c_edst[2] = {1, 0};

// ---- scratch (__device__ globals; no allocation allowed) ----
__device__ float g_h[(size_t)NTYPES * NN * HIDDIM];
__device__ float g_proj[(size_t)NTYPES * NN * 384];
__device__ float g_agg[(size_t)NTYPES * NN * HIDDIM];
__device__ float g_wcat[(size_t)NTYPES * 128 * 384];
__device__ float g_bcat[NTYPES * 384];
__device__ uint8_t g_bsplit[(size_t)NTYPES * 3 * 65536];       // B fragment images
__device__ uint4 g_pkA_hi[(size_t)NTYPES * MTILES * 8 * 32];   // A images (x / gelu(agg))
__device__ uint4 g_pkA_lo[(size_t)NTYPES * MTILES * 8 * 32];
__device__ uint4 g_pkH_hi[(size_t)NTYPES * MTILES * 8 * 32];   // h images
__device__ uint4 g_pkH_lo[(size_t)NTYPES * MTILES * 8 * 32];
__device__ int   g_deg[NETYPES * NN];
__device__ int   g_off[NETYPES * (NN + 1)];
__device__ int   g_cur[NETYPES * NN];
__device__ int   g_srcs[(size_t)NETYPES * NEDGE];
__device__ int   g_last[NTYPES * NN];

__device__ __forceinline__ float gelu_exact(float x) {
    return 0.5f * x * (1.0f + erff(x * 0.7071067811865476f));
}

// split x,y into bf16 hi pair (packed b16x2, x in low half) + lo pair
__device__ __forceinline__ uint32_t split2(float x, float y, uint32_t& lo) {
    __nv_bfloat16 hx = __float2bfloat16(x), hy = __float2bfloat16(y);
    float rx = x - __bfloat162float(hx);
    float ry = y - __bfloat162float(hy);
    __nv_bfloat16 lx = __float2bfloat16(rx), ly = __float2bfloat16(ry);
    uint16_t uhx = *(uint16_t*)&hx, uhy = *(uint16_t*)&hy;
    uint16_t ulx = *(uint16_t*)&lx, uly = *(uint16_t*)&ly;
    lo = ((uint32_t)uly << 16) | ulx;
    return ((uint32_t)uhy << 16) | uhx;
}

#define MMA_BF16(d, a, b0, b1) \
    asm volatile("mma.sync.aligned.m16n8k16.row.col.f32.bf16.bf16.f32 " \
                 "{%0,%1,%2,%3},{%4,%5,%6,%7},{%8,%9},{%0,%1,%2,%3};" \
                 : "+f"((d)[0]), "+f"((d)[1]), "+f"((d)[2]), "+f"((d)[3]) \
                 : "r"((a).x), "r"((a).y), "r"((a).z), "r"((a).w), "r"(b0), "r"(b1))

// ---------------- init ----------------
__global__ void init_kernel() {
    int idx = blockIdx.x * blockDim.x + threadIdx.x;
    if (idx < NETYPES * NN) g_deg[idx] = 0;
    if (idx < NTYPES * NN)  g_last[idx] = -1;
}

// ---------------- CSR build ----------------
__global__ void edge_count_kernel(const int* __restrict__ ei) {
    int idx = blockIdx.x * blockDim.x + threadIdx.x;
    if (idx >= NETYPES * NEDGE) return;
    int e = idx / NEDGE, j = idx % NEDGE;
    const int* base = ei + (size_t)e * 2 * NEDGE;
    int src = base[j];
    int dst = base[NEDGE + j];
    atomicAdd(&g_deg[e * NN + dst], 1);
    atomicMax(&g_last[c_esrc[e] * NN + src], j);
}

__global__ void scan_kernel() {
    int e = blockIdx.x;
    __shared__ int sh[1024];
    int tidx = threadIdx.x;
    const int CH = (NN + 1023) / 1024;
    int base = tidx * CH;
    int s = 0;
    for (int i = 0; i < CH; i++) { int id = base + i; if (id < NN) s += g_deg[e * NN + id]; }
    sh[tidx] = s;
    __syncthreads();
    for (int o = 1; o < 1024; o <<= 1) {
        int v = (tidx >= o) ? sh[tidx - o] : 0;
        __syncthreads();
        sh[tidx] += v;
        __syncthreads();
    }
    int run = sh[tidx] - s;
    for (int i = 0; i < CH; i++) {
        int id = base + i;
        if (id < NN) {
            g_off[e * (NN + 1) + id] = run;
            g_cur[e * NN + id] = run;
            run += g_deg[e * NN + id];
        }
    }
    if (tidx == 1023) g_off[e * (NN + 1) + NN] = sh[1023];
}

__global__ void edge_scatter_kernel(const int* __restrict__ ei) {
    int idx = blockIdx.x * blockDim.x + threadIdx.x;
    if (idx >= NETYPES * NEDGE) return;
    int e = idx / NEDGE, j = idx % NEDGE;
    const int* base = ei + (size_t)e * 2 * NEDGE;
    int src = base[j];
    int dst = base[NEDGE + j];
    int pos = atomicAdd(&g_cur[e * NN + dst], 1);
    g_srcs[(size_t)e * NEDGE + pos] = src;
}

// ---------------- compose Wcat = [q_w | k_w@R_att | v_w@R_msg] ----------------
__global__ void compose_kernel(const float* __restrict__ kw, const float* __restrict__ kb,
                               const float* __restrict__ qw, const float* __restrict__ qb,
                               const float* __restrict__ vw, const float* __restrict__ vb,
                               const float* __restrict__ ratt, const float* __restrict__ rmsg,
                               int l) {
    int idx = blockIdx.x * blockDim.x + threadIdx.x;
    const int total = NTYPES * 384 * 129;
    if (idx >= total) return;
    int t = idx / (384 * 129);
    int r = idx % (384 * 129);
    int j = r / 129;
    int i = r % 129;
    float val;
    if (j < 128) {
        val = (i < 128) ? qw[(((size_t)l * NTYPES + t) * 128 + i) * 128 + j]
                        : qb[((size_t)l * NTYPES + t) * 128 + j];
    } else {
        bool isK = (j < 256);
        int jo = j - (isK ? 128 : 256);
        int hh = jo >> 5, eo = jo & 31;
        int e = 0;
        for (int ee = 0; ee < NETYPES; ee++) if (c_esrc[ee] == t) e = ee;
        const float* rel = (isK ? ratt : rmsg) +
                           ((((size_t)l * NETYPES + e) * NH + hh) * DH) * DH + eo;
        float s = 0.f;
        if (i < 128) {
            const float* wr = (isK ? kw : vw) + (((size_t)l * NTYPES + t) * 128 + i) * 128 + hh * 32;
            #pragma unroll
            for (int d = 0; d < 32; d++) s += wr[d] * rel[d * 32];
        } else {
            const float* br = (isK ? kb : vb) + ((size_t)l * NTYPES + t) * 128 + hh * 32;
            #pragma unroll
            for (int d = 0; d < 32; d++) s += br[d] * rel[d * 32];
        }
        val = s;
    }
    if (i < 128) g_wcat[((size_t)t * 128 + i) * 384 + j] = val;
    else         g_bcat[t * 384 + j] = val;
}

// ---------------- A split+pack: fp32 [z][NN][128] -> mma A-fragment images ----------------
template<bool GELU>
__global__ void split_pack_kernel(const float* __restrict__ src,
                                  uint4* __restrict__ dhi, uint4* __restrict__ dlo) {
    int idx = blockIdx.x * blockDim.x + threadIdx.x;
    const int total = NTYPES * MTILES * 8 * 32;
    if (idx >= total) return;
    int lane = idx & 31;
    int s = (idx >> 5) & 7;
    int mt = (idx >> 8) % MTILES;
    int z = idx / (MTILES * 8 * 32);
    int g = lane >> 2, tig = lane & 3;
    int r0 = mt * 16 + g;
    int c0 = s * 16 + tig * 2;
    const float* S = src + (size_t)z * NN * 128;
    float2 p00 = *(const float2*)(S + (size_t)r0 * 128 + c0);
    float2 p10 = *(const float2*)(S + (size_t)(r0 + 8) * 128 + c0);
    float2 p01 = *(const float2*)(S + (size_t)r0 * 128 + c0 + 8);
    float2 p11 = *(const float2*)(S + (size_t)(r0 + 8) * 128 + c0 + 8);
    if (GELU) {
        p00.x = gelu_exact(p00.x); p00.y = gelu_exact(p00.y);
        p10.x = gelu_exact(p10.x); p10.y = gelu_exact(p10.y);
        p01.x = gelu_exact(p01.x); p01.y = gelu_exact(p01.y);
        p11.x = gelu_exact(p11.x); p11.y = gelu_exact(p11.y);
    }
    uint4 hi, lo;
    hi.x = split2(p00.x, p00.y, lo.x);
    hi.y = split2(p10.x, p10.y, lo.y);
    hi.z = split2(p01.x, p01.y, lo.z);
    hi.w = split2(p11.x, p11.y, lo.w);
    size_t o = (((size_t)z * MTILES + mt) * 8 + s) * 32 + lane;
    dhi[o] = hi;
    dlo[o] = lo;
}

// ---------------- B prep: fp32 W[k][n] -> mma B-fragment images (hi+lo interleaved) ----------------
__global__ void prep_b_kernel(const float* __restrict__ Wsrc, int Nout, int zstride) {
    int idx = blockIdx.x * blockDim.x + threadIdx.x;
    const int ntl = Nout >> 7;
    const int total = NTYPES * ntl * 8 * 16 * 32;
    if (idx >= total) return;
    int lane = idx & 31;
    int f = (idx >> 5) & 15;
    int s = (idx >> 9) & 7;
    int nt = (idx >> 12) % ntl;
    int z = idx / (ntl * 8 * 16 * 32);
    int g = lane >> 2, tig = lane & 3;
    int n = nt * 128 + f * 8 + g;
    int k0 = s * 16 + tig * 2;
    const float* W = Wsrc + (size_t)z * zstride;
    float w00 = W[(size_t)k0 * Nout + n];
    float w01 = W[(size_t)(k0 + 1) * Nout + n];
    float w10 = W[(size_t)(k0 + 8) * Nout + n];
    float w11 = W[(size_t)(k0 + 9) * Nout + n];
    uint4 q;
    q.x = split2(w00, w01, q.z);
    q.y = split2(w10, w11, q.w);
    uint4* img = (uint4*)(g_bsplit + ((size_t)z * ntl + nt) * 65536);
    img[(s * 16 + f) * 32 + lane] = q;
}

// ---------------- bf16 3-term mma GEMM ----------------
// epi: 0 none, 1 relu + edge-weight row scaling, 2 skip-gated residual.
// packHi/packLo non-null (Ntot must be 128): epilogue also emits A-fragment images.
__global__ void __launch_bounds__(256, 2)
gemm_mma(const uint4* __restrict__ Ahi, const uint4* __restrict__ Alo,
         const float* __restrict__ bias, int sB,
         float* __restrict__ C, size_t sC,
         const float* __restrict__ resid, size_t sR,
         const float* __restrict__ skipv,
         int Ntot, int epi, const float* __restrict__ ew,
         uint4* __restrict__ packHi, uint4* __restrict__ packLo) {
    extern __shared__ uint4 Bs[];  // 4096 x 16B = 64KB
    const int z = blockIdx.z, nt = blockIdx.y;
    const int tid = threadIdx.x, warp = tid >> 5, lane = tid & 31;
    const int wm = warp >> 1, wn = warp & 1;
    const int g = lane >> 2, tig = lane & 3;

    {
        const uint4* Bimg = (const uint4*)(g_bsplit + ((size_t)z * gridDim.y + nt) * 65536);
        #pragma unroll
        for (int i = 0; i < 16; i++) Bs[tid + i * 256] = Bimg[tid + i * 256];
    }
    __syncthreads();

    const int mt0 = blockIdx.x * 8 + wm * 2;
    float acc[2][8][4];
    #pragma unroll
    for (int a = 0; a < 2; a++)
        #pragma unroll
        for (int b = 0; b < 8; b++)
            #pragma unroll
            for (int c = 0; c < 4; c++) acc[a][b][c] = 0.f;

    uint4 aH[2], aL[2], nHbuf[2], nLbuf[2];
    const uint4 zero4 = make_uint4(0, 0, 0, 0);
    #pragma unroll
    for (int mt = 0; mt < 2; mt++) {
        int mtg = mt0 + mt;
        if (mtg < MTILES) {
            size_t o = (((size_t)z * MTILES + mtg) * 8 + 0) * 32 + lane;
            aH[mt] = Ahi[o]; aL[mt] = Alo[o];
        } else { aH[mt] = zero4; aL[mt] = zero4; }
    }

    for (int s = 0; s < 8; s++) {
        if (s < 7) {
            #pragma unroll
            for (int mt = 0; mt < 2; mt++) {
                int mtg = mt0 + mt;
                if (mtg < MTILES) {
                    size_t o = (((size_t)z * MTILES + mtg) * 8 + (s + 1)) * 32 + lane;
                    nHbuf[mt] = Ahi[o]; nLbuf[mt] = Alo[o];
                } else { nHbuf[mt] = zero4; nLbuf[mt] = zero4; }
            }
        }
        #pragma unroll
        for (int f = 0; f < 8; f++) {
            uint4 q = Bs[(s * 16 + wn * 8 + f) * 32 + lane];
            #pragma unroll
            for (int mt = 0; mt < 2; mt++) {
                MMA_BF16(acc[mt][f], aH[mt], q.x, q.y);   // ah*bh
                MMA_BF16(acc[mt][f], aH[mt], q.z, q.w);   // ah*bl
                MMA_BF16(acc[mt][f], aL[mt], q.x, q.y);   // al*bh
            }
        }
        #pragma unroll
        for (int mt = 0; mt < 2; mt++) { aH[mt] = nHbuf[mt]; aL[mt] = nLbuf[mt]; }
    }

    // ---- epilogue ----
    const float* biasz = bias + (size_t)z * sB;
    float* Cz = C + (size_t)z * sC;
    const float* residz = resid ? resid + (size_t)z * sR : nullptr;
    float beta = 1.f, omb = 0.f;
    if (epi == 2) {
        float sv = skipv[z];
        beta = 1.f / (1.f + expf(-sv));
        omb = 1.f - beta;
    }
    const int n0 = nt * 128 + wn * 64;
    #pragma unroll
    for (int mt = 0; mt < 2; mt++) {
        int mtg = mt0 + mt;
        if (mtg >= MTILES) continue;
        int r0 = mtg * 16 + g;
        float w0 = 1.f, w1 = 1.f;
        if (epi == 1) {
            // EDGE_SRC[e]==z => e==z; last-write-wins sigmoid edge weight
            int li0 = g_last[z * NN + r0];
            int li1 = g_last[z * NN + r0 + 8];
            if (li0 >= 0) w0 = 1.f / (1.f + expf(-ew[(size_t)z * NEDGE + li0]));
            if (li1 >= 0) w1 = 1.f / (1.f + expf(-ew[(size_t)z * NEDGE + li1]));
        }
        #pragma unroll
        for (int sl = 0; sl < 4; sl++) {
            int fe = sl * 2, fo = fe + 1;
            float ve[4], vo[4];
            {
                int c = n0 + fe * 8 + tig * 2;
                float2 b2 = *(const float2*)(biasz + c);
                ve[0] = acc[mt][fe][0] + b2.x; ve[1] = acc[mt][fe][1] + b2.y;
                ve[2] = acc[mt][fe][2] + b2.x; ve[3] = acc[mt][fe][3] + b2.y;
            }
            {
                int c = n0 + fo * 8 + tig * 2;
                float2 b2 = *(const float2*)(biasz + c);
                vo[0] = acc[mt][fo][0] + b2.x; vo[1] = acc[mt][fo][1] + b2.y;
                vo[2] = acc[mt][fo][2] + b2.x; vo[3] = acc[mt][fo][3] + b2.y;
            }
            if (epi == 1) {
                #pragma unroll
                for (int i = 0; i < 4; i++) { ve[i] = fmaxf(ve[i], 0.f); vo[i] = fmaxf(vo[i], 0.f); }
                ve[0] *= w0; ve[1] *= w0; ve[2] *= w1; ve[3] *= w1;
                vo[0] *= w0; vo[1] *= w0; vo[2] *= w1; vo[3] *= w1;
            } else if (epi == 2) {
                int ce = n0 + fe * 8 + tig * 2, co = n0 + fo * 8 + tig * 2;
                float2 ra = *(const float2*)(residz + (size_t)r0 * 128 + ce);
                float2 rb = *(const float2*)(residz + (size_t)(r0 + 8) * 128 + ce);
                float2 rc = *(const float2*)(residz + (size_t)r0 * 128 + co);
                float2 rd = *(const float2*)(residz + (size_t)(r0 + 8) * 128 + co);
                ve[0] = beta * ve[0] + omb * ra.x; ve[1] = beta * ve[1] + omb * ra.y;
                ve[2] = beta * ve[2] + omb * rb.x; ve[3] = beta * ve[3] + omb * rb.y;
                vo[0] = beta * vo[0] + omb * rc.x; vo[1] = beta * vo[1] + omb * rc.y;
                vo[2] = beta * vo[2] + omb * rd.x; vo[3] = beta * vo[3] + omb * rd.y;
            }
            {
                int ce = n0 + fe * 8 + tig * 2, co = n0 + fo * 8 + tig * 2;
                *(float2*)(Cz + (size_t)r0 * Ntot + ce)       = make_float2(ve[0], ve[1]);
                *(float2*)(Cz + (size_t)(r0 + 8) * Ntot + ce) = make_float2(ve[2], ve[3]);
                *(float2*)(Cz + (size_t)r0 * Ntot + co)       = make_float2(vo[0], vo[1]);
                *(float2*)(Cz + (size_t)(r0 + 8) * Ntot + co) = make_float2(vo[2], vo[3]);
            }
            if (packHi) {
                // fragment step s = wn*4 + sl (valid only when Ntot == 128)
                uint4 hi, lo;
                hi.x = split2(ve[0], ve[1], lo.x);
                hi.y = split2(ve[2], ve[3], lo.y);
                hi.z = split2(vo[0], vo[1], lo.z);
                hi.w = split2(vo[2], vo[3], lo.w);
                size_t o = (((size_t)z * MTILES + mtg) * 8 + (wn * 4 + sl)) * 32 + lane;
                packHi[o] = hi;
                packLo[o] = lo;
            }
        }
    }
}

// ---------------- attention + aggregation: warp per dst node, online softmax ----------------
__global__ void attn_kernel(const float* __restrict__ relp) {
    int e = blockIdx.y;
    int warp = threadIdx.x >> 5, lane = threadIdx.x & 31;
    int n = blockIdx.x * (blockDim.x >> 5) + warp;
    if (n >= NN) return;
    int t = c_edst[e], s = c_esrc[e];
    const float* projT = g_proj + (size_t)t * NN * 384;
    const float* projS = g_proj + (size_t)s * NN * 384;
    const int* offE = g_off + e * (NN + 1);
    const int* srcE = g_srcs + (size_t)e * NEDGE;
    int g = lane >> 3;
    float ascale = relp[e * NH + g] * 0.17677669529663689f;
    float4 q4 = *(const float4*)(projT + (size_t)n * 384 + lane * 4);
    int beg = offE[n], end = offE[n + 1];
    float m = -3.0e38f, ssum = 0.f;
    float4 acc = make_float4(0.f, 0.f, 0.f, 0.f);
    int p2 = beg;
    for (; p2 + 2 <= end; p2 += 2) {
        int u0 = srcE[p2], u1 = srcE[p2 + 1];
        const float* rs0 = projS + (size_t)u0 * 384;
        const float* rs1 = projS + (size_t)u1 * 384;
        float4 k0 = *(const float4*)(rs0 + 128 + lane * 4);
        float4 v0 = *(const float4*)(rs0 + 256 + lane * 4);
        float4 k1 = *(const float4*)(rs1 + 128 + lane * 4);
        float4 v1 = *(const float4*)(rs1 + 256 + lane * 4);
        float d0 = q4.x * k0.x + q4.y * k0.y + q4.z * k0.z + q4.w * k0.w;
        float d1 = q4.x * k1.x + q4.y * k1.y + q4.z * k1.z + q4.w * k1.w;
        d0 += __shfl_xor_sync(0xffffffffu, d0, 1);
        d1 += __shfl_xor_sync(0xffffffffu, d1, 1);
        d0 += __shfl_xor_sync(0xffffffffu, d0, 2);
        d1 += __shfl_xor_sync(0xffffffffu, d1, 2);
        d0 += __shfl_xor_sync(0xffffffffu, d0, 4);
        d1 += __shfl_xor_sync(0xffffffffu, d1, 4);
        float a0 = d0 * ascale, a1 = d1 * ascale;
        {
            float nm = fmaxf(m, a0);
            float sc = expf(m - nm), pe = expf(a0 - nm);
            ssum = ssum * sc + pe;
            acc.x = acc.x * sc + pe * v0.x;
            acc.y = acc.y * sc + pe * v0.y;
            acc.z = acc.z * sc + pe * v0.z;
            acc.w = acc.w * sc + pe * v0.w;
            m = nm;
        }
        {
            float nm = fmaxf(m, a1);
            float sc = expf(m - nm), pe = expf(a1 - nm);
            ssum = ssum * sc + pe;
            acc.x = acc.x * sc + pe * v1.x;
            acc.y = acc.y * sc + pe * v1.y;
            acc.z = acc.z * sc + pe * v1.z;
            acc.w = acc.w * sc + pe * v1.w;
            m = nm;
        }
    }
    for (; p2 < end; ++p2) {
        int u = srcE[p2];
        const float* rs = projS + (size_t)u * 384;
        float4 k4 = *(const float4*)(rs + 128 + lane * 4);
        float4 v4 = *(const float4*)(rs + 256 + lane * 4);
        float d = q4.x * k4.x + q4.y * k4.y + q4.z * k4.z + q4.w * k4.w;
        d += __shfl_xor_sync(0xffffffffu, d, 1);
        d += __shfl_xor_sync(0xffffffffu, d, 2);
        d += __shfl_xor_sync(0xffffffffu, d, 4);
        float a = d * ascale;
        float nm = fmaxf(m, a);
        float sc = expf(m - nm), pe = expf(a - nm);
        ssum = ssum * sc + pe;
        acc.x = acc.x * sc + pe * v4.x;
        acc.y = acc.y * sc + pe * v4.y;
        acc.z = acc.z * sc + pe * v4.z;
        acc.w = acc.w * sc + pe * v4.w;
        m = nm;
    }
    float inv = 1.f / (ssum + 1e-16f);
    float4 o = make_float4(acc.x * inv, acc.y * inv, acc.z * inv, acc.w * inv);
    *(float4*)(g_agg + ((size_t)t * NN + n) * HIDDIM + lane * 4) = o;
}

// ---------------- launch ----------------
extern "C" void kernel_launch(void* const* d_in, const int* in_sizes, int n_in,
                              void* d_out, int out_size) {
    const float* x       = (const float*)d_in[0];
    const int*   ei      = (const int*)  d_in[1];
    const float* ew      = (const float*)d_in[2];
    const float* lin_w   = (const float*)d_in[3];
    const float* lin_b   = (const float*)d_in[4];
    const float* k_w     = (const float*)d_in[5];
    const float* k_b     = (const float*)d_in[6];
    const float* q_w     = (const float*)d_in[7];
    const float* q_b     = (const float*)d_in[8];
    const float* v_w     = (const float*)d_in[9];
    const float* v_b     = (const float*)d_in[10];
    const float* a_w     = (const float*)d_in[11];
    const float* a_b     = (const float*)d_in[12];
    const float* skip    = (const float*)d_in[13];
    const float* rel_att = (const float*)d_in[14];
    const float* rel_msg = (const float*)d_in[15];
    const float* rel_p   = (const float*)d_in[16];
    float* out = (float*)d_out;

    float *ph, *pproj, *pagg, *pwcat, *pbcat;
    uint4 *pAh, *pAl, *pHh, *pHl;
    cudaGetSymbolAddress((void**)&ph,    g_h);
    cudaGetSymbolAddress((void**)&pproj, g_proj);
    cudaGetSymbolAddress((void**)&pagg,  g_agg);
    cudaGetSymbolAddress((void**)&pwcat, g_wcat);
    cudaGetSymbolAddress((void**)&pbcat, g_bcat);
    cudaGetSymbolAddress((void**)&pAh,   g_pkA_hi);
    cudaGetSymbolAddress((void**)&pAl,   g_pkA_lo);
    cudaGetSymbolAddress((void**)&pHh,   g_pkH_hi);
    cudaGetSymbolAddress((void**)&pHl,   g_pkH_lo);

    static int smem_set = 0;
    const int SMEM_GEMM = 65536;
    if (!smem_set) {
        cudaFuncSetAttribute(gemm_mma, cudaFuncAttributeMaxDynamicSharedMemorySize, SMEM_GEMM);
        smem_set = 1;
    }

    const int MB = (NN + 127) / 128;  // 391
    const int PACK_T = NTYPES * MTILES * 8 * 32;

    // CSR first (input-proj epilogue needs g_last)
    init_kernel<<<(NETYPES * NN + 255) / 256, 256>>>();
    edge_count_kernel<<<(NETYPES * NEDGE + 255) / 256, 256>>>(ei);
    scan_kernel<<<NETYPES, 1024>>>();
    edge_scatter_kernel<<<(NETYPES * NEDGE + 255) / 256, 256>>>(ei);

    // input projection + relu + edge-weight scaling, emits h (float) + packed H
    split_pack_kernel<false><<<(PACK_T + 255) / 256, 256>>>(x, pAh, pAl);
    prep_b_kernel<<<(NTYPES * 1 * 4096 + 255) / 256, 256>>>(lin_w, 128, 128 * 128);
    gemm_mma<<<dim3(MB, 1, NTYPES), 256, SMEM_GEMM>>>(
        pAh, pAl, lin_b, 128, ph, (size_t)NN * 128, nullptr, 0, nullptr,
        128, 1, ew, pHh, pHl);

    for (int l = 0; l < NL; l++) {
        compose_kernel<<<(NTYPES * 384 * 129 + 255) / 256, 256>>>(
            k_w, k_b, q_w, q_b, v_w, v_b, rel_att, rel_msg, l);

        // fused q | k_rel | v_rel projection
        prep_b_kernel<<<(NTYPES * 3 * 4096 + 255) / 256, 256>>>(pwcat, 384, 128 * 384);
        gemm_mma<<<dim3(MB, 3, NTYPES), 256, SMEM_GEMM>>>(
            pHh, pHl, pbcat, 384, pproj, (size_t)NN * 384, nullptr, 0, nullptr,
            384, 0, nullptr, nullptr, nullptr);

        attn_kernel<<<dim3((NN + 7) / 8, NETYPES), 256>>>(rel_p + l * NETYPES * NH);

        // output projection: gelu in split_pack, skip-residual + next-layer pack in epilogue
        split_pack_kernel<true><<<(PACK_T + 255) / 256, 256>>>(pagg, pAh, pAl);
        prep_b_kernel<<<(NTYPES * 1 * 4096 + 255) / 256, 256>>>(
            a_w + (size_t)l * NTYPES * 128 * 128, 128, 128 * 128);
        float* dst = (l == NL - 1) ? out : ph;
        bool last = (l == NL - 1);
        gemm_mma<<<dim3(MB, 1, NTYPES), 256, SMEM_GEMM>>>(
            pAh, pAl, a_b + (size_t)l * NTYPES * 128, 128,
            dst, (size_t)NN * 128, ph, (size_t)NN * 128,
            skip + l * NTYPES, 128, 2, nullptr,
            last ? nullptr : pHh, last ? nullptr : pHl);
    }
}